// round 13
// baseline (speedup 1.0000x reference)
#include <cuda_runtime.h>
#include <cuda_bf16.h>
#include <cuda_fp16.h>

#define N_VAR  100000
#define N_CSTR 50000
#define NEDGE  1000000
#define D      64
#define BN_EPS 1e-5f

typedef unsigned long long u64;
typedef unsigned int u32;

// ---------------- scratch ----------------
__device__ __half2 g_agg_node[N_VAR * 32];   // mean-aggregated messages, f16
__device__ __half2 g_agg_cstr[N_CSTR * 32];
__device__ int2  g_e_node[NEDGE];
__device__ int2  g_e_cstr[NEDGE];
__device__ int   g_deg_node[N_VAR];
__device__ int   g_deg_cstr[N_CSTR];
__device__ int   g_row_node[N_VAR];
__device__ int   g_row_cstr[N_CSTR];
__device__ int   g_cur_node[N_VAR];
__device__ int   g_cur_cstr[N_CSTR];
__device__ int   g_curp_node[N_VAR];         // probe counters (zeroed each replay)
__device__ int   g_curp_cstr[N_CSTR];
__device__ float g_stats_node[2 * D];
__device__ float g_stats_cstr[2 * D];
__device__ float g_scale_node[D], g_shift_node[D];
__device__ float g_scale_cstr[D], g_shift_cstr[D];
__device__ int   g_bsum_node[32];
__device__ int   g_bsum_cstr[32];

// ---------------- helpers ----------------
__device__ __forceinline__ void hmma16816(float& d0, float& d1, float& d2, float& d3,
                                          u32 a0, u32 a1, u32 a2, u32 a3,
                                          u32 b0, u32 b1) {
    asm volatile(
        "mma.sync.aligned.m16n8k16.row.col.f32.f16.f16.f32 "
        "{%0,%1,%2,%3}, {%4,%5,%6,%7}, {%8,%9}, {%0,%1,%2,%3};"
        : "+f"(d0), "+f"(d1), "+f"(d2), "+f"(d3)
        : "r"(a0), "r"(a1), "r"(a2), "r"(a3), "r"(b0), "r"(b1));
}
__device__ __forceinline__ u32 pkh(float lo, float hi) {
    __half2 h = __floats2half2_rn(lo, hi);
    return *(u32*)&h;
}

// ---------------- zero scratch ----------------
__global__ void k_zero() {
    int i = blockIdx.x * blockDim.x + threadIdx.x;
    int stride = gridDim.x * blockDim.x;
    for (int j = i; j < N_VAR; j += stride) { g_deg_node[j] = 0; g_curp_node[j] = 0; }
    for (int j = i; j < N_CSTR; j += stride) { g_deg_cstr[j] = 0; g_curp_cstr[j] = 0; }
    if (i < 2 * D) { g_stats_node[i] = 0.f; g_stats_cstr[i] = 0.f; }
}

// ---------------- BN stats (pure reduction) ----------------
__global__ void k_bnstats(const float* __restrict__ x, int n, int which) {
    float* stats = which ? g_stats_cstr : g_stats_node;
    int c = threadIdx.x;
    int step = gridDim.x * blockDim.y;
    float s = 0.f, q = 0.f;
    for (int r = blockIdx.x * blockDim.y + threadIdx.y; r < n; r += step) {
        float v = x[(size_t)r * D + c];
        s += v; q = fmaf(v, v, q);
    }
    __shared__ float shs[4][64], shq[4][64];
    shs[threadIdx.y][c] = s; shq[threadIdx.y][c] = q;
    __syncthreads();
    if (threadIdx.y == 0) {
        float S = shs[0][c] + shs[1][c] + shs[2][c] + shs[3][c];
        float Q = shq[0][c] + shq[1][c] + shq[2][c] + shq[3][c];
        atomicAdd(&stats[c], S);
        atomicAdd(&stats[D + c], Q);
    }
}

// ---------------- finalize BN scale/shift ----------------
__global__ void k_finstats(const float* __restrict__ gn, const float* __restrict__ bn,
                           const float* __restrict__ gc, const float* __restrict__ bc) {
    int c = threadIdx.x;
    if (c < D) {
        float m = g_stats_node[c] / (float)N_VAR;
        float v = g_stats_node[D + c] / (float)N_VAR - m * m;
        float sc = gn[c] * rsqrtf(v + BN_EPS);
        g_scale_node[c] = sc;
        g_shift_node[c] = fmaf(-m, sc, bn[c]);
    } else if (c < 2 * D) {
        int cc = c - D;
        float m = g_stats_cstr[cc] / (float)N_CSTR;
        float v = g_stats_cstr[D + cc] / (float)N_CSTR - m * m;
        float sc = gc[cc] * rsqrtf(v + BN_EPS);
        g_scale_cstr[cc] = sc;
        g_shift_cstr[cc] = fmaf(-m, sc, bc[cc]);
    }
}

// ---------------- degree histogram ----------------
__global__ void k_hist(const int* __restrict__ src, const int* __restrict__ dst) {
    for (int e = blockIdx.x * blockDim.x + threadIdx.x; e < NEDGE; e += gridDim.x * blockDim.x) {
        atomicAdd(&g_deg_node[dst[e]], 1);
        atomicAdd(&g_deg_cstr[src[e]], 1);
    }
}

// ---------------- scans ----------------
#define SCAN_T 256
#define SCAN_I 16
#define SCAN_CHUNK (SCAN_T * SCAN_I)
#define NB_NODE ((N_VAR + SCAN_CHUNK - 1) / SCAN_CHUNK)   // 25
#define NB_CSTR ((N_CSTR + SCAN_CHUNK - 1) / SCAN_CHUNK)  // 13

__global__ void k_scan1_all() {
    int side = (blockIdx.x >= NB_NODE);
    int blk  = side ? blockIdx.x - NB_NODE : blockIdx.x;
    const int* in = side ? g_deg_cstr : g_deg_node;
    int* out = side ? g_row_cstr : g_row_node;
    int* bsum = side ? g_bsum_cstr : g_bsum_node;
    int n = side ? N_CSTR : N_VAR;
    __shared__ int sh[SCAN_T];
    int t = threadIdx.x;
    int base = blk * SCAN_CHUNK + t * SCAN_I;
    int loc[SCAN_I];
    int s = 0;
#pragma unroll
    for (int i = 0; i < SCAN_I; i++) {
        int idx = base + i;
        int v = (idx < n) ? in[idx] : 0;
        loc[i] = s; s += v;
    }
    sh[t] = s;
    __syncthreads();
    for (int off = 1; off < SCAN_T; off <<= 1) {
        int v = (t >= off) ? sh[t - off] : 0;
        __syncthreads();
        sh[t] += v;
        __syncthreads();
    }
    int pre = (t > 0) ? sh[t - 1] : 0;
#pragma unroll
    for (int i = 0; i < SCAN_I; i++) {
        int idx = base + i;
        if (idx < n) out[idx] = pre + loc[i];
    }
    if (t == SCAN_T - 1) bsum[blk] = sh[t];
}

__global__ void k_scan2() {
    int t = threadIdx.x;
    if (t == 0) {
        int s = 0;
        for (int i = 0; i < NB_NODE; i++) { int v = g_bsum_node[i]; g_bsum_node[i] = s; s += v; }
    }
    if (t == 1) {
        int s = 0;
        for (int i = 0; i < NB_CSTR; i++) { int v = g_bsum_cstr[i]; g_bsum_cstr[i] = s; s += v; }
    }
}

__global__ void k_scan3_all() {
    int side = (blockIdx.x >= NB_NODE);
    int blk  = side ? blockIdx.x - NB_NODE : blockIdx.x;
    int* row = side ? g_row_cstr : g_row_node;
    int* cur = side ? g_cur_cstr : g_cur_node;
    const int* bsum = side ? g_bsum_cstr : g_bsum_node;
    int n = side ? N_CSTR : N_VAR;
    int add = bsum[blk];
    int base = blk * SCAN_CHUNK;
    for (int i = threadIdx.x; i < SCAN_CHUNK; i += SCAN_T) {
        int idx = base + i;
        if (idx < n) { int v = row[idx] + add; row[idx] = v; cur[idx] = v; }
    }
}

// ---------------- scatter edges into CSR slots ----------------
__global__ void k_scatter(const int* __restrict__ src, const int* __restrict__ dst,
                          const float* __restrict__ attr) {
    for (int e = blockIdx.x * blockDim.x + threadIdx.x; e < NEDGE; e += gridDim.x * blockDim.x) {
        int s = src[e], d = dst[e];
        int a = __float_as_int(attr[e]);
        int p = atomicAdd(&g_cur_node[d], 1);
        g_e_node[p] = make_int2(s, a);
        int q = atomicAdd(&g_cur_cstr[s], 1);
        g_e_cstr[q] = make_int2(d, a);
    }
}

// ---------------- scatter PROBE (profiling only) ----------------
// Identical memory behavior; offsets = g_row (stale, identical in steady-state
// replays) + zeroed counter. All writes are fully overwritten by the real
// k_scatter later (slot sets are permutations of [0,NEDGE)), so output is
// unaffected on every invocation including the first.
__global__ void k_scatter_probe(const int* __restrict__ src, const int* __restrict__ dst,
                                const float* __restrict__ attr) {
    for (int e = blockIdx.x * blockDim.x + threadIdx.x; e < NEDGE; e += gridDim.x * blockDim.x) {
        int s = src[e], d = dst[e];
        int a = __float_as_int(attr[e]);
        int c1 = atomicAdd(&g_curp_node[d], 1);
        g_e_node[min(g_row_node[d] + c1, NEDGE - 1)] = make_int2(s, a);
        int c2 = atomicAdd(&g_curp_cstr[s], 1);
        g_e_cstr[min(g_row_cstr[s] + c2, NEDGE - 1)] = make_int2(d, a);
    }
}

// ---------------- gather: warp/node, shfl broadcast, fp32 features, f16 out ----------
__global__ void k_gather_all(const float* __restrict__ xnode, const float* __restrict__ xcstr) {
    int w = (blockIdx.x * blockDim.x + threadIdx.x) >> 5;
    int lane = threadIdx.x & 31;
    int side, node;
    if (w < N_VAR) { side = 0; node = w; }
    else { node = w - N_VAR; if (node >= N_CSTR) return; side = 1; }

    const int2* __restrict__ eb = side ? g_e_cstr : g_e_node;
    const int* __restrict__ row = side ? g_row_cstr : g_row_node;
    const int* __restrict__ deg = side ? g_deg_cstr : g_deg_node;
    const float2* __restrict__ xs = (const float2*)(side ? xnode : xcstr);
    const float* __restrict__ sc = side ? g_scale_node : g_scale_cstr;
    const float* __restrict__ sf = side ? g_shift_node : g_shift_cstr;
    __half2* __restrict__ agg = side ? g_agg_cstr : g_agg_node;

    int beg = __ldg(&row[node]);
    int d = __ldg(&deg[node]);
    float2 acc = make_float2(0.f, 0.f);
    float sew = 0.f;

    for (int base = 0; base < d; base += 32) {
        int rem = d - base;
        int2 rec = make_int2(0, 0);
        if (lane < rem) rec = __ldg(&eb[beg + base + lane]);
        int m = min(rem, 32);
        for (int t = 0; t < m; t++) {
            int srcn = __shfl_sync(0xffffffffu, rec.x, t);
            float a = __int_as_float(__shfl_sync(0xffffffffu, rec.y, t));
            float2 xv = __ldg(&xs[(size_t)srcn * 32 + lane]);
            acc.x = fmaf(xv.x, a, acc.x);
            acc.y = fmaf(xv.y, a, acc.y);
            sew += a;
        }
    }
    float inv = 1.f / fmaxf((float)d, 1.f);
    float2 scl = ((const float2*)sc)[lane];
    float2 shf = ((const float2*)sf)[lane];
    agg[(size_t)node * 32 + lane] =
        __floats2half2_rn((scl.x * acc.x + shf.x * sew) * inv,
                          (scl.y * acc.y + shf.y * sew) * inv);
}
#define GATHER_BLOCKS (((N_VAR + N_CSTR) * 32 + 255) / 256)

// ---------------- output: HMMA f16 GEMM (K=128) + fp32 residual epilogue ----------
// D[128x64] = A[128x128]_f16 @ B[64x128]^T_f16   (A=[agg|xn], B=[Wrel|Wroot])
// out = relu(D + bias + xn_fp32)   (xn recomputed fp32 from xr in epilogue)
#define NOB_NODE ((N_VAR + 127) / 128)   // 782
#define NOB_CSTR ((N_CSTR + 127) / 128)  // 391
#define PADK 136                          // row stride elems: conflict-free fragments
#define SM_A_BYTES (128 * PADK * 2)       // 34816
#define SM_B_BYTES (64 * PADK * 2)        // 17408
#define HMMA_SMEM (SM_A_BYTES + SM_B_BYTES)

__global__ void __launch_bounds__(256) k_out_hmma(
        const float* __restrict__ nWrel, const float* __restrict__ nbrel,
        const float* __restrict__ nWroot, const float* __restrict__ nxraw,
        float* __restrict__ nout,
        const float* __restrict__ cWrel, const float* __restrict__ cbrel,
        const float* __restrict__ cWroot, const float* __restrict__ cxraw,
        float* __restrict__ cout) {
    int side = (blockIdx.x >= NOB_NODE);
    int blk  = side ? blockIdx.x - NOB_NODE : blockIdx.x;
    const float* __restrict__ Wrel  = side ? cWrel : nWrel;
    const float* __restrict__ brel  = side ? cbrel : nbrel;
    const float* __restrict__ Wroot = side ? cWroot : nWroot;
    const float* __restrict__ xr    = side ? cxraw : nxraw;
    float* __restrict__ outp = side ? cout : nout;
    const __half2* __restrict__ aggb = side ? g_agg_cstr : g_agg_node;
    const float* __restrict__ sc = side ? g_scale_cstr : g_scale_node;
    const float* __restrict__ sf = side ? g_shift_cstr : g_shift_node;
    int n = side ? N_CSTR : N_VAR;

    extern __shared__ __align__(16) char dynsm[];
    __half* sA = (__half*)dynsm;                     // [128][PADK]
    __half* sB = (__half*)(dynsm + SM_A_BYTES);      // [64][PADK]
    __shared__ float sBias[64], sSc[64], sSh[64];

    int tid = threadIdx.x;
    int base = blk * 128;

    if (tid < 64) {
        sBias[tid] = __ldg(&brel[tid]);
        sSc[tid] = __ldg(&sc[tid]);
        sSh[tid] = __ldg(&sf[tid]);
    }

    // ---- stage A: thread = (row m = tid>>1, half h = tid&1) ----
    {
        int m = tid >> 1, h = tid & 1;
        int row = min(base + m, n - 1);
        if (h == 0) {   // agg: 64 f16 = 8 uint4
            const uint4* arow = (const uint4*)(aggb + (size_t)row * 32);
#pragma unroll
            for (int j = 0; j < 8; j++) {
                uint4 v = __ldg(&arow[j]);
                *(uint4*)(sA + m * PADK + j * 8) = v;
            }
        } else {        // xn = scale*x+shift -> f16: 8 uint4
            const float4* xrow = (const float4*)(xr + (size_t)row * 64);
            const float4* sc4 = (const float4*)sc;
            const float4* sf4 = (const float4*)sf;
#pragma unroll
            for (int j = 0; j < 8; j++) {
                float4 x0 = __ldg(&xrow[2 * j]),  x1 = __ldg(&xrow[2 * j + 1]);
                float4 s0 = __ldg(&sc4[2 * j]),   s1 = __ldg(&sc4[2 * j + 1]);
                float4 h0 = __ldg(&sf4[2 * j]),   h1 = __ldg(&sf4[2 * j + 1]);
                uint4 v;
                v.x = pkh(fmaf(x0.x, s0.x, h0.x), fmaf(x0.y, s0.y, h0.y));
                v.y = pkh(fmaf(x0.z, s0.z, h0.z), fmaf(x0.w, s0.w, h0.w));
                v.z = pkh(fmaf(x1.x, s1.x, h1.x), fmaf(x1.y, s1.y, h1.y));
                v.w = pkh(fmaf(x1.z, s1.z, h1.z), fmaf(x1.w, s1.w, h1.w));
                *(uint4*)(sA + m * PADK + 64 + j * 8) = v;
            }
        }
    }
    // ---- stage B: tid<128: nr = tid&63, which = tid>>6 (0:Wrel, 1:Wroot) ----
    if (tid < 128) {
        int nr = tid & 63, which = tid >> 6;
        const float* Wsrc = which ? Wroot : Wrel;
        const float4* wrow = (const float4*)(Wsrc + nr * 64);
#pragma unroll
        for (int j = 0; j < 8; j++) {
            float4 a = __ldg(&wrow[2 * j]);
            float4 b = __ldg(&wrow[2 * j + 1]);
            uint4 v;
            v.x = pkh(a.x, a.y); v.y = pkh(a.z, a.w);
            v.z = pkh(b.x, b.y); v.w = pkh(b.z, b.w);
            *(uint4*)(sB + nr * PADK + which * 64 + j * 8) = v;
        }
    }
    __syncthreads();

    // ---- compute: warp w handles rows w*16 .. w*16+15, all 64 cols ----
    int w = tid >> 5, lane = tid & 31;
    int g = lane >> 2, tig = lane & 3;
    int mrow = w * 16 + g;

    float acc[8][4];
#pragma unroll
    for (int j = 0; j < 8; j++)
        acc[j][0] = acc[j][1] = acc[j][2] = acc[j][3] = 0.f;

    const u32* sAw = (const u32*)sA;
    const u32* sBw = (const u32*)sB;

#pragma unroll
    for (int kt = 0; kt < 8; kt++) {
        int k0 = kt * 16;
        u32 a0 = sAw[(mrow * PADK + k0 + 2 * tig) >> 1];
        u32 a1 = sAw[((mrow + 8) * PADK + k0 + 2 * tig) >> 1];
        u32 a2 = sAw[(mrow * PADK + k0 + 8 + 2 * tig) >> 1];
        u32 a3 = sAw[((mrow + 8) * PADK + k0 + 8 + 2 * tig) >> 1];
#pragma unroll
        for (int j = 0; j < 8; j++) {
            u32 b0 = sBw[((8 * j + g) * PADK + k0 + 2 * tig) >> 1];
            u32 b1 = sBw[((8 * j + g) * PADK + k0 + 8 + 2 * tig) >> 1];
            hmma16816(acc[j][0], acc[j][1], acc[j][2], acc[j][3], a0, a1, a2, a3, b0, b1);
        }
    }

    // ---- epilogue: out = relu(acc + bias + scale*x+shift), fp32 exact ----
    int r0 = base + w * 16 + g;
    int r1 = r0 + 8;
#pragma unroll
    for (int j = 0; j < 8; j++) {
        int c0 = 8 * j + 2 * tig;
        float bi0 = sBias[c0], bi1 = sBias[c0 + 1];
        float s0 = sSc[c0], s1 = sSc[c0 + 1];
        float h0 = sSh[c0], h1 = sSh[c0 + 1];
        if (r0 < n) {
            float2 x = *(const float2*)(xr + (size_t)r0 * 64 + c0);
            float2 o;
            o.x = fmaxf(acc[j][0] + bi0 + fmaf(x.x, s0, h0), 0.f);
            o.y = fmaxf(acc[j][1] + bi1 + fmaf(x.y, s1, h1), 0.f);
            *(float2*)(outp + (size_t)r0 * 64 + c0) = o;
        }
        if (r1 < n) {
            float2 x = *(const float2*)(xr + (size_t)r1 * 64 + c0);
            float2 o;
            o.x = fmaxf(acc[j][2] + bi0 + fmaf(x.x, s0, h0), 0.f);
            o.y = fmaxf(acc[j][3] + bi1 + fmaf(x.y, s1, h1), 0.f);
            *(float2*)(outp + (size_t)r1 * 64 + c0) = o;
        }
    }
}

// ---------------- launch ----------------
extern "C" void kernel_launch(void* const* d_in, const int* in_sizes, int n_in,
                              void* d_out, int out_size) {
    (void)in_sizes; (void)n_in; (void)out_size;
    const float* var_feats   = (const float*)d_in[0];
    const float* cstr_feats  = (const float*)d_in[1];
    const int*   edge_src    = (const int*)d_in[2];
    const int*   edge_dst    = (const int*)d_in[3];
    const float* edge_attr   = (const float*)d_in[4];
    const float* gn          = (const float*)d_in[5];
    const float* bn          = (const float*)d_in[6];
    const float* gc          = (const float*)d_in[7];
    const float* bc          = (const float*)d_in[8];
    const float* node_rel_w  = (const float*)d_in[9];
    const float* node_rel_b  = (const float*)d_in[10];
    const float* node_root_w = (const float*)d_in[11];
    const float* cstr_rel_w  = (const float*)d_in[12];
    const float* cstr_rel_b  = (const float*)d_in[13];
    const float* cstr_root_w = (const float*)d_in[14];

    float* out_node = (float*)d_out;
    float* out_cstr = out_node + (size_t)N_VAR * D;

    cudaFuncSetAttribute(k_out_hmma, cudaFuncAttributeMaxDynamicSharedMemorySize, HMMA_SMEM);

    k_zero<<<391, 256>>>();
    k_hist<<<2048, 256>>>(edge_src, edge_dst);
    k_bnstats<<<888, dim3(64, 4)>>>(var_feats, N_VAR, 0);
    // index 3 = ncu's captured slot: scatter probe (removed next round)
    k_scatter_probe<<<2048, 256>>>(edge_src, edge_dst, edge_attr);   // <- profiled
    k_bnstats<<<888, dim3(64, 4)>>>(cstr_feats, N_CSTR, 1);
    k_finstats<<<1, 128>>>(gn, bn, gc, bc);
    k_scan1_all<<<NB_NODE + NB_CSTR, SCAN_T>>>();
    k_scan2<<<1, 2>>>();
    k_scan3_all<<<NB_NODE + NB_CSTR, SCAN_T>>>();
    k_scatter<<<2048, 256>>>(edge_src, edge_dst, edge_attr);
    k_gather_all<<<GATHER_BLOCKS, 256>>>(var_feats, cstr_feats);
    k_out_hmma<<<NOB_NODE + NOB_CSTR, 256, HMMA_SMEM>>>(
        node_rel_w, node_rel_b, node_root_w, var_feats, out_node,
        cstr_rel_w, cstr_rel_b, cstr_root_w, cstr_feats, out_cstr);
}

// round 14
// speedup vs baseline: 1.1026x; 1.1026x over previous
#include <cuda_runtime.h>
#include <cuda_fp16.h>

#define N_VAR  100000
#define N_CSTR 50000
#define NEDGE  1000000
#define D      64
#define BN_EPS 1e-5f

typedef unsigned long long u64;
typedef unsigned int u32;

// ---------------- scratch ----------------
__device__ __half2 g_agg_node[N_VAR * 32];   // mean-aggregated messages, f16
__device__ __half2 g_agg_cstr[N_CSTR * 32];
__device__ int2  g_e_node[NEDGE];
__device__ int2  g_e_cstr[NEDGE];
__device__ int   g_deg_node[N_VAR];
__device__ int   g_deg_cstr[N_CSTR];
__device__ int   g_row_node[N_VAR];
__device__ int   g_row_cstr[N_CSTR];
__device__ int   g_cur_node[N_VAR];
__device__ int   g_cur_cstr[N_CSTR];
__device__ float g_stats_node[2 * D];
__device__ float g_stats_cstr[2 * D];
__device__ float g_scale_node[D], g_shift_node[D];
__device__ float g_scale_cstr[D], g_shift_cstr[D];
__device__ int   g_bsum_node[32];
__device__ int   g_bsum_cstr[32];

// ---------------- helpers ----------------
__device__ __forceinline__ void hmma16816(float& d0, float& d1, float& d2, float& d3,
                                          u32 a0, u32 a1, u32 a2, u32 a3,
                                          u32 b0, u32 b1) {
    asm volatile(
        "mma.sync.aligned.m16n8k16.row.col.f32.f16.f16.f32 "
        "{%0,%1,%2,%3}, {%4,%5,%6,%7}, {%8,%9}, {%0,%1,%2,%3};"
        : "+f"(d0), "+f"(d1), "+f"(d2), "+f"(d3)
        : "r"(a0), "r"(a1), "r"(a2), "r"(a3), "r"(b0), "r"(b1));
}
__device__ __forceinline__ u32 pkh(float lo, float hi) {
    __half2 h = __floats2half2_rn(lo, hi);
    return *(u32*)&h;
}

// ---------------- zero scratch ----------------
__global__ void k_zero() {
    int i = blockIdx.x * blockDim.x + threadIdx.x;
    int stride = gridDim.x * blockDim.x;
    for (int j = i; j < N_VAR; j += stride) g_deg_node[j] = 0;
    for (int j = i; j < N_CSTR; j += stride) g_deg_cstr[j] = 0;
    if (i < 2 * D) { g_stats_node[i] = 0.f; g_stats_cstr[i] = 0.f; }
}

// ---------------- BN stats (pure reduction) ----------------
__global__ void k_bnstats(const float* __restrict__ x, int n, int which) {
    float* stats = which ? g_stats_cstr : g_stats_node;
    int c = threadIdx.x;
    int step = gridDim.x * blockDim.y;
    float s = 0.f, q = 0.f;
    for (int r = blockIdx.x * blockDim.y + threadIdx.y; r < n; r += step) {
        float v = x[(size_t)r * D + c];
        s += v; q = fmaf(v, v, q);
    }
    __shared__ float shs[4][64], shq[4][64];
    shs[threadIdx.y][c] = s; shq[threadIdx.y][c] = q;
    __syncthreads();
    if (threadIdx.y == 0) {
        float S = shs[0][c] + shs[1][c] + shs[2][c] + shs[3][c];
        float Q = shq[0][c] + shq[1][c] + shq[2][c] + shq[3][c];
        atomicAdd(&stats[c], S);
        atomicAdd(&stats[D + c], Q);
    }
}

// ---------------- finalize BN scale/shift ----------------
__global__ void k_finstats(const float* __restrict__ gn, const float* __restrict__ bn,
                           const float* __restrict__ gc, const float* __restrict__ bc) {
    int c = threadIdx.x;
    if (c < D) {
        float m = g_stats_node[c] / (float)N_VAR;
        float v = g_stats_node[D + c] / (float)N_VAR - m * m;
        float sc = gn[c] * rsqrtf(v + BN_EPS);
        g_scale_node[c] = sc;
        g_shift_node[c] = fmaf(-m, sc, bn[c]);
    } else if (c < 2 * D) {
        int cc = c - D;
        float m = g_stats_cstr[cc] / (float)N_CSTR;
        float v = g_stats_cstr[D + cc] / (float)N_CSTR - m * m;
        float sc = gc[cc] * rsqrtf(v + BN_EPS);
        g_scale_cstr[cc] = sc;
        g_shift_cstr[cc] = fmaf(-m, sc, bc[cc]);
    }
}

// ---------------- degree histogram (4 edges/thread, batched REDG) ----------------
#define E4 (NEDGE / 4)   // 250000
__global__ void k_hist(const int4* __restrict__ src4, const int4* __restrict__ dst4) {
    for (int i = blockIdx.x * blockDim.x + threadIdx.x; i < E4; i += gridDim.x * blockDim.x) {
        int4 s = __ldg(&src4[i]);
        int4 d = __ldg(&dst4[i]);
        atomicAdd(&g_deg_node[d.x], 1);
        atomicAdd(&g_deg_node[d.y], 1);
        atomicAdd(&g_deg_node[d.z], 1);
        atomicAdd(&g_deg_node[d.w], 1);
        atomicAdd(&g_deg_cstr[s.x], 1);
        atomicAdd(&g_deg_cstr[s.y], 1);
        atomicAdd(&g_deg_cstr[s.z], 1);
        atomicAdd(&g_deg_cstr[s.w], 1);
    }
}

// ---------------- scans ----------------
#define SCAN_T 256
#define SCAN_I 16
#define SCAN_CHUNK (SCAN_T * SCAN_I)
#define NB_NODE ((N_VAR + SCAN_CHUNK - 1) / SCAN_CHUNK)   // 25
#define NB_CSTR ((N_CSTR + SCAN_CHUNK - 1) / SCAN_CHUNK)  // 13

__global__ void k_scan1_all() {
    int side = (blockIdx.x >= NB_NODE);
    int blk  = side ? blockIdx.x - NB_NODE : blockIdx.x;
    const int* in = side ? g_deg_cstr : g_deg_node;
    int* out = side ? g_row_cstr : g_row_node;
    int* bsum = side ? g_bsum_cstr : g_bsum_node;
    int n = side ? N_CSTR : N_VAR;
    __shared__ int sh[SCAN_T];
    int t = threadIdx.x;
    int base = blk * SCAN_CHUNK + t * SCAN_I;
    int loc[SCAN_I];
    int s = 0;
#pragma unroll
    for (int i = 0; i < SCAN_I; i++) {
        int idx = base + i;
        int v = (idx < n) ? in[idx] : 0;
        loc[i] = s; s += v;
    }
    sh[t] = s;
    __syncthreads();
    for (int off = 1; off < SCAN_T; off <<= 1) {
        int v = (t >= off) ? sh[t - off] : 0;
        __syncthreads();
        sh[t] += v;
        __syncthreads();
    }
    int pre = (t > 0) ? sh[t - 1] : 0;
#pragma unroll
    for (int i = 0; i < SCAN_I; i++) {
        int idx = base + i;
        if (idx < n) out[idx] = pre + loc[i];
    }
    if (t == SCAN_T - 1) bsum[blk] = sh[t];
}

__global__ void k_scan2() {
    int t = threadIdx.x;
    if (t == 0) {
        int s = 0;
        for (int i = 0; i < NB_NODE; i++) { int v = g_bsum_node[i]; g_bsum_node[i] = s; s += v; }
    }
    if (t == 1) {
        int s = 0;
        for (int i = 0; i < NB_CSTR; i++) { int v = g_bsum_cstr[i]; g_bsum_cstr[i] = s; s += v; }
    }
}

__global__ void k_scan3_all() {
    int side = (blockIdx.x >= NB_NODE);
    int blk  = side ? blockIdx.x - NB_NODE : blockIdx.x;
    int* row = side ? g_row_cstr : g_row_node;
    int* cur = side ? g_cur_cstr : g_cur_node;
    const int* bsum = side ? g_bsum_cstr : g_bsum_node;
    int n = side ? N_CSTR : N_VAR;
    int add = bsum[blk];
    int base = blk * SCAN_CHUNK;
    for (int i = threadIdx.x; i < SCAN_CHUNK; i += SCAN_T) {
        int idx = base + i;
        if (idx < n) { int v = row[idx] + add; row[idx] = v; cur[idx] = v; }
    }
}

// ---------------- scatter: 4 edges/thread, batched atomics then stores ----------------
__global__ void k_scatter(const int4* __restrict__ src4, const int4* __restrict__ dst4,
                          const float4* __restrict__ attr4) {
    for (int i = blockIdx.x * blockDim.x + threadIdx.x; i < E4; i += gridDim.x * blockDim.x) {
        int4 s = __ldg(&src4[i]);
        int4 d = __ldg(&dst4[i]);
        float4 a = __ldg(&attr4[i]);
        // 8 independent atomics in flight
        int p0 = atomicAdd(&g_cur_node[d.x], 1);
        int p1 = atomicAdd(&g_cur_node[d.y], 1);
        int p2 = atomicAdd(&g_cur_node[d.z], 1);
        int p3 = atomicAdd(&g_cur_node[d.w], 1);
        int q0 = atomicAdd(&g_cur_cstr[s.x], 1);
        int q1 = atomicAdd(&g_cur_cstr[s.y], 1);
        int q2 = atomicAdd(&g_cur_cstr[s.z], 1);
        int q3 = atomicAdd(&g_cur_cstr[s.w], 1);
        g_e_node[p0] = make_int2(s.x, __float_as_int(a.x));
        g_e_node[p1] = make_int2(s.y, __float_as_int(a.y));
        g_e_node[p2] = make_int2(s.z, __float_as_int(a.z));
        g_e_node[p3] = make_int2(s.w, __float_as_int(a.w));
        g_e_cstr[q0] = make_int2(d.x, __float_as_int(a.x));
        g_e_cstr[q1] = make_int2(d.y, __float_as_int(a.y));
        g_e_cstr[q2] = make_int2(d.z, __float_as_int(a.z));
        g_e_cstr[q3] = make_int2(d.w, __float_as_int(a.w));
    }
}

// ---------------- gather: warp/node, shfl broadcast, fp32 features, f16 out ----------
__global__ void k_gather_all(const float* __restrict__ xnode, const float* __restrict__ xcstr) {
    int w = (blockIdx.x * blockDim.x + threadIdx.x) >> 5;
    int lane = threadIdx.x & 31;
    int side, node;
    if (w < N_VAR) { side = 0; node = w; }
    else { node = w - N_VAR; if (node >= N_CSTR) return; side = 1; }

    const int2* __restrict__ eb = side ? g_e_cstr : g_e_node;
    const int* __restrict__ row = side ? g_row_cstr : g_row_node;
    const int* __restrict__ deg = side ? g_deg_cstr : g_deg_node;
    const float2* __restrict__ xs = (const float2*)(side ? xnode : xcstr);
    const float* __restrict__ sc = side ? g_scale_node : g_scale_cstr;
    const float* __restrict__ sf = side ? g_shift_node : g_shift_cstr;
    __half2* __restrict__ agg = side ? g_agg_cstr : g_agg_node;

    int beg = __ldg(&row[node]);
    int d = __ldg(&deg[node]);
    float2 acc = make_float2(0.f, 0.f);
    float sew = 0.f;

    for (int base = 0; base < d; base += 32) {
        int rem = d - base;
        int2 rec = make_int2(0, 0);
        if (lane < rem) rec = __ldg(&eb[beg + base + lane]);
        int m = min(rem, 32);
        for (int t = 0; t < m; t++) {
            int srcn = __shfl_sync(0xffffffffu, rec.x, t);
            float a = __int_as_float(__shfl_sync(0xffffffffu, rec.y, t));
            float2 xv = __ldg(&xs[(size_t)srcn * 32 + lane]);
            acc.x = fmaf(xv.x, a, acc.x);
            acc.y = fmaf(xv.y, a, acc.y);
            sew += a;
        }
    }
    float inv = 1.f / fmaxf((float)d, 1.f);
    float2 scl = ((const float2*)sc)[lane];
    float2 shf = ((const float2*)sf)[lane];
    agg[(size_t)node * 32 + lane] =
        __floats2half2_rn((scl.x * acc.x + shf.x * sew) * inv,
                          (scl.y * acc.y + shf.y * sew) * inv);
}
#define GATHER_BLOCKS (((N_VAR + N_CSTR) * 32 + 255) / 256)

// ---------------- output: HMMA f16 GEMM (K=128) + fp32 residual epilogue ----------
// D[128x64] = A[128x128]_f16 @ B[64x128]^T_f16   (A=[agg|xn], B=[Wrel|Wroot])
// out = relu(D + bias + xn_fp32)
#define NOB_NODE ((N_VAR + 127) / 128)   // 782
#define NOB_CSTR ((N_CSTR + 127) / 128)  // 391
#define PADK 136
#define SM_A_BYTES (128 * PADK * 2)       // 34816
#define SM_B_BYTES (64 * PADK * 2)        // 17408
#define HMMA_SMEM (SM_A_BYTES + SM_B_BYTES)

__global__ void __launch_bounds__(256) k_out_hmma(
        const float* __restrict__ nWrel, const float* __restrict__ nbrel,
        const float* __restrict__ nWroot, const float* __restrict__ nxraw,
        float* __restrict__ nout,
        const float* __restrict__ cWrel, const float* __restrict__ cbrel,
        const float* __restrict__ cWroot, const float* __restrict__ cxraw,
        float* __restrict__ cout) {
    int side = (blockIdx.x >= NOB_NODE);
    int blk  = side ? blockIdx.x - NOB_NODE : blockIdx.x;
    const float* __restrict__ Wrel  = side ? cWrel : nWrel;
    const float* __restrict__ brel  = side ? cbrel : nbrel;
    const float* __restrict__ Wroot = side ? cWroot : nWroot;
    const float* __restrict__ xr    = side ? cxraw : nxraw;
    float* __restrict__ outp = side ? cout : nout;
    const __half2* __restrict__ aggb = side ? g_agg_cstr : g_agg_node;
    const float* __restrict__ sc = side ? g_scale_cstr : g_scale_node;
    const float* __restrict__ sf = side ? g_shift_cstr : g_shift_node;
    int n = side ? N_CSTR : N_VAR;

    extern __shared__ __align__(16) char dynsm[];
    __half* sA = (__half*)dynsm;                     // [128][PADK]
    __half* sB = (__half*)(dynsm + SM_A_BYTES);      // [64][PADK]
    __shared__ float sBias[64], sSc[64], sSh[64];

    int tid = threadIdx.x;
    int base = blk * 128;

    if (tid < 64) {
        sBias[tid] = __ldg(&brel[tid]);
        sSc[tid] = __ldg(&sc[tid]);
        sSh[tid] = __ldg(&sf[tid]);
    }

    // ---- stage A: thread = (row m = tid>>1, half h = tid&1) ----
    {
        int m = tid >> 1, h = tid & 1;
        int row = min(base + m, n - 1);
        if (h == 0) {   // agg: 64 f16 = 8 uint4
            const uint4* arow = (const uint4*)(aggb + (size_t)row * 32);
#pragma unroll
            for (int j = 0; j < 8; j++) {
                uint4 v = __ldg(&arow[j]);
                *(uint4*)(sA + m * PADK + j * 8) = v;
            }
        } else {        // xn = scale*x+shift -> f16
            const float4* xrow = (const float4*)(xr + (size_t)row * 64);
            const float4* sc4 = (const float4*)sc;
            const float4* sf4 = (const float4*)sf;
#pragma unroll
            for (int j = 0; j < 8; j++) {
                float4 x0 = __ldg(&xrow[2 * j]),  x1 = __ldg(&xrow[2 * j + 1]);
                float4 s0 = __ldg(&sc4[2 * j]),   s1 = __ldg(&sc4[2 * j + 1]);
                float4 h0 = __ldg(&sf4[2 * j]),   h1 = __ldg(&sf4[2 * j + 1]);
                uint4 v;
                v.x = pkh(fmaf(x0.x, s0.x, h0.x), fmaf(x0.y, s0.y, h0.y));
                v.y = pkh(fmaf(x0.z, s0.z, h0.z), fmaf(x0.w, s0.w, h0.w));
                v.z = pkh(fmaf(x1.x, s1.x, h1.x), fmaf(x1.y, s1.y, h1.y));
                v.w = pkh(fmaf(x1.z, s1.z, h1.z), fmaf(x1.w, s1.w, h1.w));
                *(uint4*)(sA + m * PADK + 64 + j * 8) = v;
            }
        }
    }
    // ---- stage B: tid<128: nr = tid&63, which = tid>>6 (0:Wrel, 1:Wroot) ----
    if (tid < 128) {
        int nr = tid & 63, which = tid >> 6;
        const float* Wsrc = which ? Wroot : Wrel;
        const float4* wrow = (const float4*)(Wsrc + nr * 64);
#pragma unroll
        for (int j = 0; j < 8; j++) {
            float4 a = __ldg(&wrow[2 * j]);
            float4 b = __ldg(&wrow[2 * j + 1]);
            uint4 v;
            v.x = pkh(a.x, a.y); v.y = pkh(a.z, a.w);
            v.z = pkh(b.x, b.y); v.w = pkh(b.z, b.w);
            *(uint4*)(sB + nr * PADK + which * 64 + j * 8) = v;
        }
    }
    __syncthreads();

    // ---- compute: warp w handles rows w*16 .. w*16+15, all 64 cols ----
    int w = tid >> 5, lane = tid & 31;
    int g = lane >> 2, tig = lane & 3;
    int mrow = w * 16 + g;

    float acc[8][4];
#pragma unroll
    for (int j = 0; j < 8; j++)
        acc[j][0] = acc[j][1] = acc[j][2] = acc[j][3] = 0.f;

    const u32* sAw = (const u32*)sA;
    const u32* sBw = (const u32*)sB;

#pragma unroll
    for (int kt = 0; kt < 8; kt++) {
        int k0 = kt * 16;
        u32 a0 = sAw[(mrow * PADK + k0 + 2 * tig) >> 1];
        u32 a1 = sAw[((mrow + 8) * PADK + k0 + 2 * tig) >> 1];
        u32 a2 = sAw[(mrow * PADK + k0 + 8 + 2 * tig) >> 1];
        u32 a3 = sAw[((mrow + 8) * PADK + k0 + 8 + 2 * tig) >> 1];
#pragma unroll
        for (int j = 0; j < 8; j++) {
            u32 b0 = sBw[((8 * j + g) * PADK + k0 + 2 * tig) >> 1];
            u32 b1 = sBw[((8 * j + g) * PADK + k0 + 8 + 2 * tig) >> 1];
            hmma16816(acc[j][0], acc[j][1], acc[j][2], acc[j][3], a0, a1, a2, a3, b0, b1);
        }
    }

    // ---- epilogue: out = relu(acc + bias + scale*x+shift), fp32 exact ----
    int r0 = base + w * 16 + g;
    int r1 = r0 + 8;
#pragma unroll
    for (int j = 0; j < 8; j++) {
        int c0 = 8 * j + 2 * tig;
        float bi0 = sBias[c0], bi1 = sBias[c0 + 1];
        float s0 = sSc[c0], s1 = sSc[c0 + 1];
        float h0 = sSh[c0], h1 = sSh[c0 + 1];
        if (r0 < n) {
            float2 x = *(const float2*)(xr + (size_t)r0 * 64 + c0);
            float2 o;
            o.x = fmaxf(acc[j][0] + bi0 + fmaf(x.x, s0, h0), 0.f);
            o.y = fmaxf(acc[j][1] + bi1 + fmaf(x.y, s1, h1), 0.f);
            *(float2*)(outp + (size_t)r0 * 64 + c0) = o;
        }
        if (r1 < n) {
            float2 x = *(const float2*)(xr + (size_t)r1 * 64 + c0);
            float2 o;
            o.x = fmaxf(acc[j][2] + bi0 + fmaf(x.x, s0, h0), 0.f);
            o.y = fmaxf(acc[j][3] + bi1 + fmaf(x.y, s1, h1), 0.f);
            *(float2*)(outp + (size_t)r1 * 64 + c0) = o;
        }
    }
}

// ---------------- launch ----------------
extern "C" void kernel_launch(void* const* d_in, const int* in_sizes, int n_in,
                              void* d_out, int out_size) {
    (void)in_sizes; (void)n_in; (void)out_size;
    const float* var_feats   = (const float*)d_in[0];
    const float* cstr_feats  = (const float*)d_in[1];
    const int*   edge_src    = (const int*)d_in[2];
    const int*   edge_dst    = (const int*)d_in[3];
    const float* edge_attr   = (const float*)d_in[4];
    const float* gn          = (const float*)d_in[5];
    const float* bn          = (const float*)d_in[6];
    const float* gc          = (const float*)d_in[7];
    const float* bc          = (const float*)d_in[8];
    const float* node_rel_w  = (const float*)d_in[9];
    const float* node_rel_b  = (const float*)d_in[10];
    const float* node_root_w = (const float*)d_in[11];
    const float* cstr_rel_w  = (const float*)d_in[12];
    const float* cstr_rel_b  = (const float*)d_in[13];
    const float* cstr_root_w = (const float*)d_in[14];

    float* out_node = (float*)d_out;
    float* out_cstr = out_node + (size_t)N_VAR * D;

    cudaFuncSetAttribute(k_out_hmma, cudaFuncAttributeMaxDynamicSharedMemorySize, HMMA_SMEM);

    k_zero<<<391, 256>>>();
    k_hist<<<1024, 256>>>((const int4*)edge_src, (const int4*)edge_dst);
    k_bnstats<<<888, dim3(64, 4)>>>(var_feats, N_VAR, 0);
    k_bnstats<<<888, dim3(64, 4)>>>(cstr_feats, N_CSTR, 1);   // <- profiled slot
    k_finstats<<<1, 128>>>(gn, bn, gc, bc);
    k_scan1_all<<<NB_NODE + NB_CSTR, SCAN_T>>>();
    k_scan2<<<1, 2>>>();
    k_scan3_all<<<NB_NODE + NB_CSTR, SCAN_T>>>();
    k_scatter<<<1024, 256>>>((const int4*)edge_src, (const int4*)edge_dst,
                             (const float4*)edge_attr);
    k_gather_all<<<GATHER_BLOCKS, 256>>>(var_feats, cstr_feats);
    k_out_hmma<<<NOB_NODE + NOB_CSTR, 256, HMMA_SMEM>>>(
        node_rel_w, node_rel_b, node_root_w, var_feats, out_node,
        cstr_rel_w, cstr_rel_b, cstr_root_w, cstr_feats, out_cstr);
}

// round 15
// speedup vs baseline: 1.1485x; 1.0416x over previous
#include <cuda_runtime.h>
#include <cuda_fp16.h>

#define N_VAR  100000
#define N_CSTR 50000
#define NEDGE  1000000
#define D      64
#define BN_EPS 1e-5f

typedef unsigned long long u64;
typedef unsigned int u32;

// ---------------- scratch ----------------
__device__ __half2 g_agg_node[N_VAR * 32];   // mean-aggregated messages, f16
__device__ __half2 g_agg_cstr[N_CSTR * 32];
__device__ int2  g_e_node[NEDGE];
__device__ int2  g_e_cstr[NEDGE];
__device__ int   g_rank_node[NEDGE];         // per-edge rank within dst bucket
__device__ int   g_rank_cstr[NEDGE];         // per-edge rank within src bucket
__device__ int   g_deg_node[N_VAR];
__device__ int   g_deg_cstr[N_CSTR];
__device__ int   g_row_node[N_VAR];
__device__ int   g_row_cstr[N_CSTR];
__device__ float g_stats_node[2 * D];
__device__ float g_stats_cstr[2 * D];
__device__ float g_scale_node[D], g_shift_node[D];
__device__ float g_scale_cstr[D], g_shift_cstr[D];
__device__ int   g_bsum_node[32];
__device__ int   g_bsum_cstr[32];

// ---------------- helpers ----------------
__device__ __forceinline__ void hmma16816(float& d0, float& d1, float& d2, float& d3,
                                          u32 a0, u32 a1, u32 a2, u32 a3,
                                          u32 b0, u32 b1) {
    asm volatile(
        "mma.sync.aligned.m16n8k16.row.col.f32.f16.f16.f32 "
        "{%0,%1,%2,%3}, {%4,%5,%6,%7}, {%8,%9}, {%0,%1,%2,%3};"
        : "+f"(d0), "+f"(d1), "+f"(d2), "+f"(d3)
        : "r"(a0), "r"(a1), "r"(a2), "r"(a3), "r"(b0), "r"(b1));
}
__device__ __forceinline__ u32 pkh(float lo, float hi) {
    __half2 h = __floats2half2_rn(lo, hi);
    return *(u32*)&h;
}

// ---------------- zero scratch ----------------
__global__ void k_zero() {
    int i = blockIdx.x * blockDim.x + threadIdx.x;
    int stride = gridDim.x * blockDim.x;
    for (int j = i; j < N_VAR; j += stride) g_deg_node[j] = 0;
    for (int j = i; j < N_CSTR; j += stride) g_deg_cstr[j] = 0;
    if (i < 2 * D) { g_stats_node[i] = 0.f; g_stats_cstr[i] = 0.f; }
}

// ---------------- BN stats (pure reduction) ----------------
__global__ void k_bnstats(const float* __restrict__ x, int n, int which) {
    float* stats = which ? g_stats_cstr : g_stats_node;
    int c = threadIdx.x;
    int step = gridDim.x * blockDim.y;
    float s = 0.f, q = 0.f;
    for (int r = blockIdx.x * blockDim.y + threadIdx.y; r < n; r += step) {
        float v = x[(size_t)r * D + c];
        s += v; q = fmaf(v, v, q);
    }
    __shared__ float shs[4][64], shq[4][64];
    shs[threadIdx.y][c] = s; shq[threadIdx.y][c] = q;
    __syncthreads();
    if (threadIdx.y == 0) {
        float S = shs[0][c] + shs[1][c] + shs[2][c] + shs[3][c];
        float Q = shq[0][c] + shq[1][c] + shq[2][c] + shq[3][c];
        atomicAdd(&stats[c], S);
        atomicAdd(&stats[D + c], Q);
    }
}

// ---------------- finalize BN scale/shift ----------------
__global__ void k_finstats(const float* __restrict__ gn, const float* __restrict__ bn,
                           const float* __restrict__ gc, const float* __restrict__ bc) {
    int c = threadIdx.x;
    if (c < D) {
        float m = g_stats_node[c] / (float)N_VAR;
        float v = g_stats_node[D + c] / (float)N_VAR - m * m;
        float sc = gn[c] * rsqrtf(v + BN_EPS);
        g_scale_node[c] = sc;
        g_shift_node[c] = fmaf(-m, sc, bn[c]);
    } else if (c < 2 * D) {
        int cc = c - D;
        float m = g_stats_cstr[cc] / (float)N_CSTR;
        float v = g_stats_cstr[D + cc] / (float)N_CSTR - m * m;
        float sc = gc[cc] * rsqrtf(v + BN_EPS);
        g_scale_cstr[cc] = sc;
        g_shift_cstr[cc] = fmaf(-m, sc, bc[cc]);
    }
}

// ---------------- hist + rank: the ONLY atomic pass ----------------
// Keeps the atomicAdd return as the edge's rank within its bucket.
__global__ void k_hist_rank(const int* __restrict__ src, const int* __restrict__ dst) {
    for (int e = blockIdx.x * blockDim.x + threadIdx.x; e < NEDGE; e += gridDim.x * blockDim.x) {
        int d = __ldg(&dst[e]);
        int s = __ldg(&src[e]);
        g_rank_node[e] = atomicAdd(&g_deg_node[d], 1);
        g_rank_cstr[e] = atomicAdd(&g_deg_cstr[s], 1);
    }
}

// ---------------- scans ----------------
#define SCAN_T 256
#define SCAN_I 16
#define SCAN_CHUNK (SCAN_T * SCAN_I)
#define NB_NODE ((N_VAR + SCAN_CHUNK - 1) / SCAN_CHUNK)   // 25
#define NB_CSTR ((N_CSTR + SCAN_CHUNK - 1) / SCAN_CHUNK)  // 13

__global__ void k_scan1_all() {
    int side = (blockIdx.x >= NB_NODE);
    int blk  = side ? blockIdx.x - NB_NODE : blockIdx.x;
    const int* in = side ? g_deg_cstr : g_deg_node;
    int* out = side ? g_row_cstr : g_row_node;
    int* bsum = side ? g_bsum_cstr : g_bsum_node;
    int n = side ? N_CSTR : N_VAR;
    __shared__ int sh[SCAN_T];
    int t = threadIdx.x;
    int base = blk * SCAN_CHUNK + t * SCAN_I;
    int loc[SCAN_I];
    int s = 0;
#pragma unroll
    for (int i = 0; i < SCAN_I; i++) {
        int idx = base + i;
        int v = (idx < n) ? in[idx] : 0;
        loc[i] = s; s += v;
    }
    sh[t] = s;
    __syncthreads();
    for (int off = 1; off < SCAN_T; off <<= 1) {
        int v = (t >= off) ? sh[t - off] : 0;
        __syncthreads();
        sh[t] += v;
        __syncthreads();
    }
    int pre = (t > 0) ? sh[t - 1] : 0;
#pragma unroll
    for (int i = 0; i < SCAN_I; i++) {
        int idx = base + i;
        if (idx < n) out[idx] = pre + loc[i];
    }
    if (t == SCAN_T - 1) bsum[blk] = sh[t];
}

__global__ void k_scan2() {
    int t = threadIdx.x;
    if (t == 0) {
        int s = 0;
        for (int i = 0; i < NB_NODE; i++) { int v = g_bsum_node[i]; g_bsum_node[i] = s; s += v; }
    }
    if (t == 1) {
        int s = 0;
        for (int i = 0; i < NB_CSTR; i++) { int v = g_bsum_cstr[i]; g_bsum_cstr[i] = s; s += v; }
    }
}

__global__ void k_scan3_all() {
    int side = (blockIdx.x >= NB_NODE);
    int blk  = side ? blockIdx.x - NB_NODE : blockIdx.x;
    int* row = side ? g_row_cstr : g_row_node;
    const int* bsum = side ? g_bsum_cstr : g_bsum_node;
    int n = side ? N_CSTR : N_VAR;
    int add = bsum[blk];
    int base = blk * SCAN_CHUNK;
    for (int i = threadIdx.x; i < SCAN_CHUNK; i += SCAN_T) {
        int idx = base + i;
        if (idx < n) row[idx] += add;
    }
}

// ---------------- scatter: pure stores, slot = row[bucket] + rank ----------------
__global__ void k_scatter_store(const int* __restrict__ src, const int* __restrict__ dst,
                                const float* __restrict__ attr) {
    for (int e = blockIdx.x * blockDim.x + threadIdx.x; e < NEDGE; e += gridDim.x * blockDim.x) {
        int s = __ldg(&src[e]);
        int d = __ldg(&dst[e]);
        int a = __float_as_int(__ldg(&attr[e]));
        int rn = __ldg(&g_rank_node[e]);
        int rc = __ldg(&g_rank_cstr[e]);
        int pn = __ldg(&g_row_node[d]) + rn;
        int pc = __ldg(&g_row_cstr[s]) + rc;
        g_e_node[pn] = make_int2(s, a);
        g_e_cstr[pc] = make_int2(d, a);
    }
}

// ---------------- gather: warp/node, shfl broadcast, fp32 features, f16 out ----------
__global__ void k_gather_all(const float* __restrict__ xnode, const float* __restrict__ xcstr) {
    int w = (blockIdx.x * blockDim.x + threadIdx.x) >> 5;
    int lane = threadIdx.x & 31;
    int side, node;
    if (w < N_VAR) { side = 0; node = w; }
    else { node = w - N_VAR; if (node >= N_CSTR) return; side = 1; }

    const int2* __restrict__ eb = side ? g_e_cstr : g_e_node;
    const int* __restrict__ row = side ? g_row_cstr : g_row_node;
    const int* __restrict__ deg = side ? g_deg_cstr : g_deg_node;
    const float2* __restrict__ xs = (const float2*)(side ? xnode : xcstr);
    const float* __restrict__ sc = side ? g_scale_node : g_scale_cstr;
    const float* __restrict__ sf = side ? g_shift_node : g_shift_cstr;
    __half2* __restrict__ agg = side ? g_agg_cstr : g_agg_node;

    int beg = __ldg(&row[node]);
    int d = __ldg(&deg[node]);
    float2 acc = make_float2(0.f, 0.f);
    float sew = 0.f;

    for (int base = 0; base < d; base += 32) {
        int rem = d - base;
        int2 rec = make_int2(0, 0);
        if (lane < rem) rec = __ldg(&eb[beg + base + lane]);
        int m = min(rem, 32);
        for (int t = 0; t < m; t++) {
            int srcn = __shfl_sync(0xffffffffu, rec.x, t);
            float a = __int_as_float(__shfl_sync(0xffffffffu, rec.y, t));
            float2 xv = __ldg(&xs[(size_t)srcn * 32 + lane]);
            acc.x = fmaf(xv.x, a, acc.x);
            acc.y = fmaf(xv.y, a, acc.y);
            sew += a;
        }
    }
    float inv = 1.f / fmaxf((float)d, 1.f);
    float2 scl = ((const float2*)sc)[lane];
    float2 shf = ((const float2*)sf)[lane];
    agg[(size_t)node * 32 + lane] =
        __floats2half2_rn((scl.x * acc.x + shf.x * sew) * inv,
                          (scl.y * acc.y + shf.y * sew) * inv);
}
#define GATHER_BLOCKS (((N_VAR + N_CSTR) * 32 + 255) / 256)

// ---------------- output: HMMA f16 GEMM (K=128) + fp32 residual epilogue ----------
#define NOB_NODE ((N_VAR + 127) / 128)   // 782
#define NOB_CSTR ((N_CSTR + 127) / 128)  // 391
#define PADK 136
#define SM_A_BYTES (128 * PADK * 2)       // 34816
#define SM_B_BYTES (64 * PADK * 2)        // 17408
#define HMMA_SMEM (SM_A_BYTES + SM_B_BYTES)

__global__ void __launch_bounds__(256) k_out_hmma(
        const float* __restrict__ nWrel, const float* __restrict__ nbrel,
        const float* __restrict__ nWroot, const float* __restrict__ nxraw,
        float* __restrict__ nout,
        const float* __restrict__ cWrel, const float* __restrict__ cbrel,
        const float* __restrict__ cWroot, const float* __restrict__ cxraw,
        float* __restrict__ cout) {
    int side = (blockIdx.x >= NOB_NODE);
    int blk  = side ? blockIdx.x - NOB_NODE : blockIdx.x;
    const float* __restrict__ Wrel  = side ? cWrel : nWrel;
    const float* __restrict__ brel  = side ? cbrel : nbrel;
    const float* __restrict__ Wroot = side ? cWroot : nWroot;
    const float* __restrict__ xr    = side ? cxraw : nxraw;
    float* __restrict__ outp = side ? cout : nout;
    const __half2* __restrict__ aggb = side ? g_agg_cstr : g_agg_node;
    const float* __restrict__ sc = side ? g_scale_cstr : g_scale_node;
    const float* __restrict__ sf = side ? g_shift_cstr : g_shift_node;
    int n = side ? N_CSTR : N_VAR;

    extern __shared__ __align__(16) char dynsm[];
    __half* sA = (__half*)dynsm;                     // [128][PADK]
    __half* sB = (__half*)(dynsm + SM_A_BYTES);      // [64][PADK]
    __shared__ float sBias[64], sSc[64], sSh[64];

    int tid = threadIdx.x;
    int base = blk * 128;

    if (tid < 64) {
        sBias[tid] = __ldg(&brel[tid]);
        sSc[tid] = __ldg(&sc[tid]);
        sSh[tid] = __ldg(&sf[tid]);
    }

    // ---- stage A: thread = (row m = tid>>1, half h = tid&1) ----
    {
        int m = tid >> 1, h = tid & 1;
        int row = min(base + m, n - 1);
        if (h == 0) {   // agg: 64 f16 = 8 uint4
            const uint4* arow = (const uint4*)(aggb + (size_t)row * 32);
#pragma unroll
            for (int j = 0; j < 8; j++) {
                uint4 v = __ldg(&arow[j]);
                *(uint4*)(sA + m * PADK + j * 8) = v;
            }
        } else {        // xn = scale*x+shift -> f16
            const float4* xrow = (const float4*)(xr + (size_t)row * 64);
            const float4* sc4 = (const float4*)sc;
            const float4* sf4 = (const float4*)sf;
#pragma unroll
            for (int j = 0; j < 8; j++) {
                float4 x0 = __ldg(&xrow[2 * j]),  x1 = __ldg(&xrow[2 * j + 1]);
                float4 s0 = __ldg(&sc4[2 * j]),   s1 = __ldg(&sc4[2 * j + 1]);
                float4 h0 = __ldg(&sf4[2 * j]),   h1 = __ldg(&sf4[2 * j + 1]);
                uint4 v;
                v.x = pkh(fmaf(x0.x, s0.x, h0.x), fmaf(x0.y, s0.y, h0.y));
                v.y = pkh(fmaf(x0.z, s0.z, h0.z), fmaf(x0.w, s0.w, h0.w));
                v.z = pkh(fmaf(x1.x, s1.x, h1.x), fmaf(x1.y, s1.y, h1.y));
                v.w = pkh(fmaf(x1.z, s1.z, h1.z), fmaf(x1.w, s1.w, h1.w));
                *(uint4*)(sA + m * PADK + 64 + j * 8) = v;
            }
        }
    }
    // ---- stage B: tid<128: nr = tid&63, which = tid>>6 (0:Wrel, 1:Wroot) ----
    if (tid < 128) {
        int nr = tid & 63, which = tid >> 6;
        const float* Wsrc = which ? Wroot : Wrel;
        const float4* wrow = (const float4*)(Wsrc + nr * 64);
#pragma unroll
        for (int j = 0; j < 8; j++) {
            float4 a = __ldg(&wrow[2 * j]);
            float4 b = __ldg(&wrow[2 * j + 1]);
            uint4 v;
            v.x = pkh(a.x, a.y); v.y = pkh(a.z, a.w);
            v.z = pkh(b.x, b.y); v.w = pkh(b.z, b.w);
            *(uint4*)(sB + nr * PADK + which * 64 + j * 8) = v;
        }
    }
    __syncthreads();

    // ---- compute: warp w handles rows w*16 .. w*16+15, all 64 cols ----
    int w = tid >> 5, lane = tid & 31;
    int g = lane >> 2, tig = lane & 3;
    int mrow = w * 16 + g;

    float acc[8][4];
#pragma unroll
    for (int j = 0; j < 8; j++)
        acc[j][0] = acc[j][1] = acc[j][2] = acc[j][3] = 0.f;

    const u32* sAw = (const u32*)sA;
    const u32* sBw = (const u32*)sB;

#pragma unroll
    for (int kt = 0; kt < 8; kt++) {
        int k0 = kt * 16;
        u32 a0 = sAw[(mrow * PADK + k0 + 2 * tig) >> 1];
        u32 a1 = sAw[((mrow + 8) * PADK + k0 + 2 * tig) >> 1];
        u32 a2 = sAw[(mrow * PADK + k0 + 8 + 2 * tig) >> 1];
        u32 a3 = sAw[((mrow + 8) * PADK + k0 + 8 + 2 * tig) >> 1];
#pragma unroll
        for (int j = 0; j < 8; j++) {
            u32 b0 = sBw[((8 * j + g) * PADK + k0 + 2 * tig) >> 1];
            u32 b1 = sBw[((8 * j + g) * PADK + k0 + 8 + 2 * tig) >> 1];
            hmma16816(acc[j][0], acc[j][1], acc[j][2], acc[j][3], a0, a1, a2, a3, b0, b1);
        }
    }

    // ---- epilogue: out = relu(acc + bias + scale*x+shift), fp32 exact ----
    int r0 = base + w * 16 + g;
    int r1 = r0 + 8;
#pragma unroll
    for (int j = 0; j < 8; j++) {
        int c0 = 8 * j + 2 * tig;
        float bi0 = sBias[c0], bi1 = sBias[c0 + 1];
        float s0 = sSc[c0], s1 = sSc[c0 + 1];
        float h0 = sSh[c0], h1 = sSh[c0 + 1];
        if (r0 < n) {
            float2 x = *(const float2*)(xr + (size_t)r0 * 64 + c0);
            float2 o;
            o.x = fmaxf(acc[j][0] + bi0 + fmaf(x.x, s0, h0), 0.f);
            o.y = fmaxf(acc[j][1] + bi1 + fmaf(x.y, s1, h1), 0.f);
            *(float2*)(outp + (size_t)r0 * 64 + c0) = o;
        }
        if (r1 < n) {
            float2 x = *(const float2*)(xr + (size_t)r1 * 64 + c0);
            float2 o;
            o.x = fmaxf(acc[j][2] + bi0 + fmaf(x.x, s0, h0), 0.f);
            o.y = fmaxf(acc[j][3] + bi1 + fmaf(x.y, s1, h1), 0.f);
            *(float2*)(outp + (size_t)r1 * 64 + c0) = o;
        }
    }
}

// ---------------- launch ----------------
extern "C" void kernel_launch(void* const* d_in, const int* in_sizes, int n_in,
                              void* d_out, int out_size) {
    (void)in_sizes; (void)n_in; (void)out_size;
    const float* var_feats   = (const float*)d_in[0];
    const float* cstr_feats  = (const float*)d_in[1];
    const int*   edge_src    = (const int*)d_in[2];
    const int*   edge_dst    = (const int*)d_in[3];
    const float* edge_attr   = (const float*)d_in[4];
    const float* gn          = (const float*)d_in[5];
    const float* bn          = (const float*)d_in[6];
    const float* gc          = (const float*)d_in[7];
    const float* bc          = (const float*)d_in[8];
    const float* node_rel_w  = (const float*)d_in[9];
    const float* node_rel_b  = (const float*)d_in[10];
    const float* node_root_w = (const float*)d_in[11];
    const float* cstr_rel_w  = (const float*)d_in[12];
    const float* cstr_rel_b  = (const float*)d_in[13];
    const float* cstr_root_w = (const float*)d_in[14];

    float* out_node = (float*)d_out;
    float* out_cstr = out_node + (size_t)N_VAR * D;

    cudaFuncSetAttribute(k_out_hmma, cudaFuncAttributeMaxDynamicSharedMemorySize, HMMA_SMEM);

    k_zero<<<391, 256>>>();
    k_bnstats<<<888, dim3(64, 4)>>>(var_feats, N_VAR, 0);
    k_bnstats<<<888, dim3(64, 4)>>>(cstr_feats, N_CSTR, 1);
    k_hist_rank<<<2048, 256>>>(edge_src, edge_dst);           // <- profiled slot
    k_finstats<<<1, 128>>>(gn, bn, gc, bc);
    k_scan1_all<<<NB_NODE + NB_CSTR, SCAN_T>>>();
    k_scan2<<<1, 2>>>();
    k_scan3_all<<<NB_NODE + NB_CSTR, SCAN_T>>>();
    k_scatter_store<<<2048, 256>>>(edge_src, edge_dst, edge_attr);
    k_gather_all<<<GATHER_BLOCKS, 256>>>(var_feats, cstr_feats);
    k_out_hmma<<<NOB_NODE + NOB_CSTR, 256, HMMA_SMEM>>>(
        node_rel_w, node_rel_b, node_root_w, var_feats, out_node,
        cstr_rel_w, cstr_rel_b, cstr_root_w, cstr_feats, out_cstr);
}